// round 11
// baseline (speedup 1.0000x reference)
#include <cuda_runtime.h>
#include <math.h>

#define BATCH 16
#define NPTS  200000
#define NG    (NPTS/4)          // point-groups per batch (4 pts/group)
#define SZ    224
#define PIX   (SZ*SZ)
#define EPSF  1e-8f
#define MMB   48                // minmax blocks per batch

// ---------------- scratch (static __device__, no allocations) ----------------
__device__ float4   g_acc4[BATCH*PIX];   // per pixel: (wsum, zn*w, nx*w, ny*w)
__device__ float    g_acc1[BATCH*PIX];   // per pixel: nz*w
__device__ float    g_part[BATCH*MMB*6]; // per-block partials: xmn,xmx,ymn,ymx,zmn,zmx
__device__ int      g_cnt[BATCH];        // done counters (self-resetting)
__device__ float    g_tr[BATCH*6];       // per batch: xmn,invx, ymn,invy, zmn,invz
__device__ unsigned g_cmm[2];            // global combined min,max (order-encoded)

// monotonic float<->uint encoding so atomicMin/Max on unsigned == float min/max
__device__ __forceinline__ unsigned fenc(float f){
    unsigned u = __float_as_uint(f);
    return (u & 0x80000000u) ? ~u : (u | 0x80000000u);
}
__device__ __forceinline__ float fdec(unsigned u){
    return __uint_as_float((u & 0x80000000u) ? (u & 0x7fffffffu) : ~u);
}

// ---------------- kernel 1: fused zero + per-batch minmax + prep --------------
// grid = (MMB, BATCH). Each block zeroes a slice of the accumulators, computes
// a partial min/max of its batch's points, then the last finishing block of
// each batch reduces the partials into g_tr (recip-multiply transforms) and
// resets that batch's counter (graph-replay safe). Block (0,y=0)'s finisher
// also re-arms g_cmm.
__global__ void k_begin(const float4* __restrict__ pts4){
    int b = blockIdx.y;
    int blk = blockIdx.x;
    // ---- phase 1: zero accumulators (independent of minmax data) ----
    {
        int nb = gridDim.x*gridDim.y;
        int gi = (b*gridDim.x + blk)*blockDim.x + threadIdx.x;
        int stride = nb*blockDim.x;
        for (int idx = gi; idx < BATCH*PIX; idx += stride){
            g_acc4[idx] = make_float4(0.f,0.f,0.f,0.f);
            g_acc1[idx] = 0.f;
        }
    }
    // ---- phase 2: per-batch min/max over float4 groups ----
    const float4* p = pts4 + (size_t)b*NG*3;
    float mn0= INFINITY, mn1= INFINITY, mn2= INFINITY;
    float mx0=-INFINITY, mx1=-INFINITY, mx2=-INFINITY;
    for (int g = blk*blockDim.x + threadIdx.x; g < NG; g += gridDim.x*blockDim.x){
        float4 a = p[3*g+0];           // x0 y0 z0 x1
        float4 c = p[3*g+1];           // y1 z1 x2 y2
        float4 d = p[3*g+2];           // z2 x3 y3 z3
        mn0 = fminf(mn0, fminf(fminf(a.x, a.w), fminf(c.z, d.y)));
        mx0 = fmaxf(mx0, fmaxf(fmaxf(a.x, a.w), fmaxf(c.z, d.y)));
        mn1 = fminf(mn1, fminf(fminf(a.y, c.x), fminf(c.w, d.z)));
        mx1 = fmaxf(mx1, fmaxf(fmaxf(a.y, c.x), fmaxf(c.w, d.z)));
        mn2 = fminf(mn2, fminf(fminf(a.z, c.y), fminf(d.x, d.w)));
        mx2 = fmaxf(mx2, fmaxf(fmaxf(a.z, c.y), fmaxf(d.x, d.w)));
    }
    #pragma unroll
    for (int o = 16; o; o >>= 1){
        mn0 = fminf(mn0, __shfl_xor_sync(0xffffffffu, mn0, o));
        mx0 = fmaxf(mx0, __shfl_xor_sync(0xffffffffu, mx0, o));
        mn1 = fminf(mn1, __shfl_xor_sync(0xffffffffu, mn1, o));
        mx1 = fmaxf(mx1, __shfl_xor_sync(0xffffffffu, mx1, o));
        mn2 = fminf(mn2, __shfl_xor_sync(0xffffffffu, mn2, o));
        mx2 = fmaxf(mx2, __shfl_xor_sync(0xffffffffu, mx2, o));
    }
    __shared__ float smn[8][3], smx[8][3];
    __shared__ bool s_last;
    int w = threadIdx.x >> 5, l = threadIdx.x & 31;
    int nw = blockDim.x >> 5;
    if (l == 0){
        smn[w][0]=mn0; smn[w][1]=mn1; smn[w][2]=mn2;
        smx[w][0]=mx0; smx[w][1]=mx1; smx[w][2]=mx2;
    }
    __syncthreads();
    if (threadIdx.x == 0){
        for (int k = 1; k < nw; k++){
            mn0 = fminf(mn0, smn[k][0]); mx0 = fmaxf(mx0, smx[k][0]);
            mn1 = fminf(mn1, smn[k][1]); mx1 = fmaxf(mx1, smx[k][1]);
            mn2 = fminf(mn2, smn[k][2]); mx2 = fmaxf(mx2, smx[k][2]);
        }
        float* pp = g_part + (b*MMB + blk)*6;
        pp[0]=mn0; pp[1]=mx0; pp[2]=mn1; pp[3]=mx1; pp[4]=mn2; pp[5]=mx2;
        __threadfence();
        int t = atomicAdd(&g_cnt[b], 1);
        s_last = (t == MMB-1);
    }
    __syncthreads();
    // ---- phase 3: last block of this batch reduces partials -> g_tr ----
    if (s_last && threadIdx.x == 0){
        float amn0= INFINITY, amn1= INFINITY, amn2= INFINITY;
        float amx0=-INFINITY, amx1=-INFINITY, amx2=-INFINITY;
        for (int k = 0; k < MMB; k++){
            const float* pp = g_part + (b*MMB + k)*6;
            amn0 = fminf(amn0, pp[0]); amx0 = fmaxf(amx0, pp[1]);
            amn1 = fminf(amn1, pp[2]); amx1 = fmaxf(amx1, pp[3]);
            amn2 = fminf(amn2, pp[4]); amx2 = fmaxf(amx2, pp[5]);
        }
        g_tr[b*6+0] = amn0;
        g_tr[b*6+1] = __fdiv_rn(1.f, __fadd_rn(__fsub_rn(amx0, amn0), EPSF));
        g_tr[b*6+2] = amn1;
        g_tr[b*6+3] = __fdiv_rn(1.f, __fadd_rn(__fsub_rn(amx1, amn1), EPSF));
        g_tr[b*6+4] = amn2;
        g_tr[b*6+5] = __fdiv_rn(1.f, __fadd_rn(__fsub_rn(amx2, amn2), EPSF));
        g_cnt[b] = 0;                       // re-arm for next graph replay
        if (b == 0){ g_cmm[0] = 0xFFFFFFFFu; g_cmm[1] = 0u; }
    }
}

// ---------------- kernel 2: scatter-add, 4 points/thread, LDG.128 -------------
__device__ __forceinline__ void scatter_pt(
    float x, float y, float z, float d, float nx, float ny, float nz,
    float xmn, float ivx, float ymn, float ivy, float zmn, float ivz, int base)
{
    float w = __fdiv_rn(1.f, __fadd_rn(1.f, expf(-d)));
    float fx = __fmul_rn(__fmul_rn(__fsub_rn(x, xmn), ivx), 223.0f);
    float fy = __fmul_rn(__fmul_rn(__fsub_rn(y, ymn), ivy), 223.0f);
    int xp = min(max((int)fx, 0), SZ-1);
    int yp = min(max((int)fy, 0), SZ-1);
    float zn = __fmul_rn(__fsub_rn(z, zmn), ivz);
    int pix = base + yp*SZ + xp;
    atomicAdd(&g_acc4[pix], make_float4(w, __fmul_rn(zn, w),
                                        __fmul_rn(nx, w), __fmul_rn(ny, w)));
    atomicAdd(&g_acc1[pix], __fmul_rn(nz, w));
}

__global__ void __launch_bounds__(256, 6)
k_scatter(const float4* __restrict__ pts4,
          const float4* __restrict__ dens4,
          const float4* __restrict__ nrm4){
    int g = blockIdx.x*blockDim.x + threadIdx.x;   // group of 4 points
    if (g >= BATCH*NG) return;
    int b = g / NG;                                 // NPTS%4==0: no straddle
    const float* tr = g_tr + b*6;
    float xmn = tr[0], ivx = tr[1];
    float ymn = tr[2], ivy = tr[3];
    float zmn = tr[4], ivz = tr[5];
    int base = b*PIX;

    float4 p0 = pts4[3*g+0];   // x0 y0 z0 x1
    float4 p1 = pts4[3*g+1];   // y1 z1 x2 y2
    float4 p2 = pts4[3*g+2];   // z2 x3 y3 z3
    float4 dd = dens4[g];
    float4 n0 = nrm4[3*g+0];
    float4 n1 = nrm4[3*g+1];
    float4 n2 = nrm4[3*g+2];

    scatter_pt(p0.x, p0.y, p0.z, dd.x, n0.x, n0.y, n0.z, xmn,ivx,ymn,ivy,zmn,ivz, base);
    scatter_pt(p0.w, p1.x, p1.y, dd.y, n0.w, n1.x, n1.y, xmn,ivx,ymn,ivy,zmn,ivz, base);
    scatter_pt(p1.z, p1.w, p2.x, dd.z, n1.z, n1.w, n2.x, xmn,ivx,ymn,ivy,zmn,ivz, base);
    scatter_pt(p2.y, p2.z, p2.w, dd.w, n2.y, n2.z, n2.w, xmn,ivx,ymn,ivy,zmn,ivz, base);
}

// ---------------- kernel 3: per-pixel finalize + global min/max ---------------
__global__ void k_final(float* __restrict__ out){
    int idx = blockIdx.x*blockDim.x + threadIdx.x;
    float lmin =  INFINITY, lmax = -INFINITY;
    if (idx < BATCH*PIX){
        float4 a  = g_acc4[idx];
        float anz = g_acc1[idx];
        float safe = (a.x > 0.f) ? a.x : 1.f;
        float depth = __fdiv_rn(a.y, safe);       // invalid pixel: 0/1 == 0, matches ref
        float nx = __fdiv_rn(a.z, safe);
        float ny = __fdiv_rn(a.w, safe);
        float nz = __fdiv_rn(anz, safe);
        float ss = __fadd_rn(__fadd_rn(__fadd_rn(__fmul_rn(nx,nx), __fmul_rn(ny,ny)),
                                       __fmul_rn(nz,nz)), EPSF);
        float rn = __fsqrt_rn(ss);
        float c0 = depth;
        float c1 = __fmul_rn(__fadd_rn(__fdiv_rn(nx, rn), 1.f), 0.5f);
        float c2 = __fmul_rn(__fadd_rn(__fdiv_rn(ny, rn), 1.f), 0.5f);
        int b = idx / PIX, p = idx - b*PIX;
        out[(b*3+0)*PIX + p] = c0;
        out[(b*3+1)*PIX + p] = c1;
        out[(b*3+2)*PIX + p] = c2;
        lmin = fminf(c0, fminf(c1, c2));
        lmax = fmaxf(c0, fmaxf(c1, c2));
    }
    #pragma unroll
    for (int o = 16; o; o >>= 1){
        lmin = fminf(lmin, __shfl_xor_sync(0xffffffffu, lmin, o));
        lmax = fmaxf(lmax, __shfl_xor_sync(0xffffffffu, lmax, o));
    }
    __shared__ float smn[8], smx[8];
    int w = threadIdx.x >> 5, l = threadIdx.x & 31;
    int nw = blockDim.x >> 5;
    if (l == 0){ smn[w] = lmin; smx[w] = lmax; }
    __syncthreads();
    if (threadIdx.x == 0){
        for (int k = 1; k < nw; k++){
            lmin = fminf(lmin, smn[k]);
            lmax = fmaxf(lmax, smx[k]);
        }
        atomicMin(&g_cmm[0], fenc(lmin));
        atomicMax(&g_cmm[1], fenc(lmax));
    }
}

// ---------------- kernel 4: global min-max normalize --------------------------
__global__ void k_norm(float* __restrict__ out, int n){
    float cmn = fdec(g_cmm[0]);
    float cmx = fdec(g_cmm[1]);
    float inv = __fdiv_rn(1.f, __fadd_rn(__fsub_rn(cmx, cmn), EPSF));
    int i = blockIdx.x*blockDim.x + threadIdx.x;
    if (i < n) out[i] = __fmul_rn(__fsub_rn(out[i], cmn), inv);
}

// ---------------- launch ------------------------------------------------------
extern "C" void kernel_launch(void* const* d_in, const int* in_sizes, int n_in,
                              void* d_out, int out_size){
    const float4* pts4  = (const float4*)d_in[0];   // [16, 200000, 3] as float4 groups
    const float4* dens4 = (const float4*)d_in[1];   // [16, 200000, 1]
    const float4* nrm4  = (const float4*)d_in[2];   // [16, 200000, 3]
    float* out = (float*)d_out;                     // [16, 3, 224, 224]

    k_begin<<<dim3(MMB, BATCH), 256>>>(pts4);
    k_scatter<<<(BATCH*NG + 255)/256, 256>>>(pts4, dens4, nrm4);
    k_final<<<(BATCH*PIX + 255)/256, 256>>>(out);
    k_norm<<<(3*BATCH*PIX + 255)/256, 256>>>(out, 3*BATCH*PIX);
}

// round 12
// speedup vs baseline: 1.0205x; 1.0205x over previous
#include <cuda_runtime.h>
#include <math.h>

#define BATCH 16
#define NPTS  200000
#define NG4   (NPTS/4)          // float4 groups per batch (minmax)
#define NG2   (NPTS/2)          // 2-point groups per batch (scatter)
#define SZ    224
#define PIX   (SZ*SZ)
#define EPSF  1e-8f
#define MMB   48                // minmax blocks per batch

// ---------------- scratch (static __device__, no allocations) ----------------
__device__ float4   g_acc4[BATCH*PIX];   // per pixel: (wsum, zn*w, nx*w, ny*w)
__device__ float    g_acc1[BATCH*PIX];   // per pixel: nz*w
__device__ float    g_part[BATCH*MMB*6]; // per-block partials
__device__ int      g_cnt[BATCH];        // done counters (self-resetting)
__device__ float    g_tr[BATCH*6];       // per batch: xmn,invx, ymn,invy, zmn,invz
__device__ unsigned g_cmm[2];            // global combined min,max (order-encoded)

__device__ __forceinline__ unsigned fenc(float f){
    unsigned u = __float_as_uint(f);
    return (u & 0x80000000u) ? ~u : (u | 0x80000000u);
}
__device__ __forceinline__ float fdec(unsigned u){
    return __uint_as_float((u & 0x80000000u) ? (u & 0x7fffffffu) : ~u);
}

// ---------------- kernel 1: fused zero + per-batch minmax + prep --------------
__global__ void k_begin(const float4* __restrict__ pts4){
    int b = blockIdx.y;
    int blk = blockIdx.x;
    // phase 1: zero accumulators
    {
        int nb = gridDim.x*gridDim.y;
        int gi = (b*gridDim.x + blk)*blockDim.x + threadIdx.x;
        int stride = nb*blockDim.x;
        for (int idx = gi; idx < BATCH*PIX; idx += stride){
            g_acc4[idx] = make_float4(0.f,0.f,0.f,0.f);
            g_acc1[idx] = 0.f;
        }
    }
    // phase 2: per-batch min/max over float4 groups
    const float4* p = pts4 + (size_t)b*NG4*3;
    float mn0= INFINITY, mn1= INFINITY, mn2= INFINITY;
    float mx0=-INFINITY, mx1=-INFINITY, mx2=-INFINITY;
    for (int g = blk*blockDim.x + threadIdx.x; g < NG4; g += gridDim.x*blockDim.x){
        float4 a = p[3*g+0];           // x0 y0 z0 x1
        float4 c = p[3*g+1];           // y1 z1 x2 y2
        float4 d = p[3*g+2];           // z2 x3 y3 z3
        mn0 = fminf(mn0, fminf(fminf(a.x, a.w), fminf(c.z, d.y)));
        mx0 = fmaxf(mx0, fmaxf(fmaxf(a.x, a.w), fmaxf(c.z, d.y)));
        mn1 = fminf(mn1, fminf(fminf(a.y, c.x), fminf(c.w, d.z)));
        mx1 = fmaxf(mx1, fmaxf(fmaxf(a.y, c.x), fmaxf(c.w, d.z)));
        mn2 = fminf(mn2, fminf(fminf(a.z, c.y), fminf(d.x, d.w)));
        mx2 = fmaxf(mx2, fmaxf(fmaxf(a.z, c.y), fmaxf(d.x, d.w)));
    }
    #pragma unroll
    for (int o = 16; o; o >>= 1){
        mn0 = fminf(mn0, __shfl_xor_sync(0xffffffffu, mn0, o));
        mx0 = fmaxf(mx0, __shfl_xor_sync(0xffffffffu, mx0, o));
        mn1 = fminf(mn1, __shfl_xor_sync(0xffffffffu, mn1, o));
        mx1 = fmaxf(mx1, __shfl_xor_sync(0xffffffffu, mx1, o));
        mn2 = fminf(mn2, __shfl_xor_sync(0xffffffffu, mn2, o));
        mx2 = fmaxf(mx2, __shfl_xor_sync(0xffffffffu, mx2, o));
    }
    __shared__ float smn[8][3], smx[8][3];
    __shared__ bool s_last;
    int w = threadIdx.x >> 5, l = threadIdx.x & 31;
    int nw = blockDim.x >> 5;
    if (l == 0){
        smn[w][0]=mn0; smn[w][1]=mn1; smn[w][2]=mn2;
        smx[w][0]=mx0; smx[w][1]=mx1; smx[w][2]=mx2;
    }
    __syncthreads();
    if (threadIdx.x == 0){
        for (int k = 1; k < nw; k++){
            mn0 = fminf(mn0, smn[k][0]); mx0 = fmaxf(mx0, smx[k][0]);
            mn1 = fminf(mn1, smn[k][1]); mx1 = fmaxf(mx1, smx[k][1]);
            mn2 = fminf(mn2, smn[k][2]); mx2 = fmaxf(mx2, smx[k][2]);
        }
        float* pp = g_part + (b*MMB + blk)*6;
        pp[0]=mn0; pp[1]=mx0; pp[2]=mn1; pp[3]=mx1; pp[4]=mn2; pp[5]=mx2;
        __threadfence();
        int t = atomicAdd(&g_cnt[b], 1);
        s_last = (t == MMB-1);
    }
    __syncthreads();
    // phase 3: last block per batch reduces partials -> g_tr, re-arms counters
    if (s_last && threadIdx.x == 0){
        float amn0= INFINITY, amn1= INFINITY, amn2= INFINITY;
        float amx0=-INFINITY, amx1=-INFINITY, amx2=-INFINITY;
        for (int k = 0; k < MMB; k++){
            const float* pp = g_part + (b*MMB + k)*6;
            amn0 = fminf(amn0, pp[0]); amx0 = fmaxf(amx0, pp[1]);
            amn1 = fminf(amn1, pp[2]); amx1 = fmaxf(amx1, pp[3]);
            amn2 = fminf(amn2, pp[4]); amx2 = fmaxf(amx2, pp[5]);
        }
        g_tr[b*6+0] = amn0;
        g_tr[b*6+1] = __fdiv_rn(1.f, __fadd_rn(__fsub_rn(amx0, amn0), EPSF));
        g_tr[b*6+2] = amn1;
        g_tr[b*6+3] = __fdiv_rn(1.f, __fadd_rn(__fsub_rn(amx1, amn1), EPSF));
        g_tr[b*6+4] = amn2;
        g_tr[b*6+5] = __fdiv_rn(1.f, __fadd_rn(__fsub_rn(amx2, amn2), EPSF));
        g_cnt[b] = 0;
        if (b == 0){ g_cmm[0] = 0xFFFFFFFFu; g_cmm[1] = 0u; }
    }
}

// ---------------- kernel 2: scatter-add, 2 points/thread, LDG.64 --------------
__device__ __forceinline__ void scatter_pt(
    float x, float y, float z, float d, float nx, float ny, float nz,
    float xmn, float ivx, float ymn, float ivy, float zmn, float ivz, int base)
{
    float w = __fdiv_rn(1.f, __fadd_rn(1.f, expf(-d)));
    float fx = __fmul_rn(__fmul_rn(__fsub_rn(x, xmn), ivx), 223.0f);
    float fy = __fmul_rn(__fmul_rn(__fsub_rn(y, ymn), ivy), 223.0f);
    int xp = min(max((int)fx, 0), SZ-1);
    int yp = min(max((int)fy, 0), SZ-1);
    float zn = __fmul_rn(__fsub_rn(z, zmn), ivz);
    int pix = base + yp*SZ + xp;
    atomicAdd(&g_acc4[pix], make_float4(w, __fmul_rn(zn, w),
                                        __fmul_rn(nx, w), __fmul_rn(ny, w)));
    atomicAdd(&g_acc1[pix], __fmul_rn(nz, w));
}

__global__ void k_scatter(const float2* __restrict__ pts2,
                          const float2* __restrict__ dens2,
                          const float2* __restrict__ nrm2){
    int g = blockIdx.x*blockDim.x + threadIdx.x;   // pair of points
    if (g >= BATCH*NG2) return;
    int b = g / NG2;                                // NPTS%2==0: no straddle
    const float* tr = g_tr + b*6;
    float xmn = tr[0], ivx = tr[1];
    float ymn = tr[2], ivy = tr[3];
    float zmn = tr[4], ivz = tr[5];
    int base = b*PIX;

    float2 p0 = pts2[3*g+0];   // x0 y0
    float2 p1 = pts2[3*g+1];   // z0 x1
    float2 p2 = pts2[3*g+2];   // y1 z1
    float2 dd = dens2[g];      // d0 d1
    float2 n0 = nrm2[3*g+0];
    float2 n1 = nrm2[3*g+1];
    float2 n2 = nrm2[3*g+2];

    scatter_pt(p0.x, p0.y, p1.x, dd.x, n0.x, n0.y, n1.x, xmn,ivx,ymn,ivy,zmn,ivz, base);
    scatter_pt(p1.y, p2.x, p2.y, dd.y, n1.y, n2.x, n2.y, xmn,ivx,ymn,ivy,zmn,ivz, base);
}

// ---------------- kernel 3: per-pixel finalize (x4) + global min/max ----------
__global__ void k_final(float* __restrict__ out){
    int q = blockIdx.x*blockDim.x + threadIdx.x;   // 4 pixels
    float lmin =  INFINITY, lmax = -INFINITY;
    if (q < (BATCH*PIX)/4){
        int idx = q*4;
        int b = idx / PIX, p = idx - b*PIX;        // PIX%4==0: same b for all 4
        const float4* a1v = (const float4*)&g_acc1[idx];
        float4 anz = *a1v;
        float c0[4], c1[4], c2[4];
        #pragma unroll
        for (int k = 0; k < 4; k++){
            float4 a = g_acc4[idx+k];
            float az = (&anz.x)[k];
            float safe = (a.x > 0.f) ? a.x : 1.f;
            float depth = __fdiv_rn(a.y, safe);
            float nx = __fdiv_rn(a.z, safe);
            float ny = __fdiv_rn(a.w, safe);
            float nz = __fdiv_rn(az, safe);
            float ss = __fadd_rn(__fadd_rn(__fadd_rn(__fmul_rn(nx,nx), __fmul_rn(ny,ny)),
                                           __fmul_rn(nz,nz)), EPSF);
            float rn = __fsqrt_rn(ss);
            c0[k] = depth;
            c1[k] = __fmul_rn(__fadd_rn(__fdiv_rn(nx, rn), 1.f), 0.5f);
            c2[k] = __fmul_rn(__fadd_rn(__fdiv_rn(ny, rn), 1.f), 0.5f);
            lmin = fminf(lmin, fminf(c0[k], fminf(c1[k], c2[k])));
            lmax = fmaxf(lmax, fmaxf(c0[k], fmaxf(c1[k], c2[k])));
        }
        *(float4*)&out[(b*3+0)*PIX + p] = make_float4(c0[0],c0[1],c0[2],c0[3]);
        *(float4*)&out[(b*3+1)*PIX + p] = make_float4(c1[0],c1[1],c1[2],c1[3]);
        *(float4*)&out[(b*3+2)*PIX + p] = make_float4(c2[0],c2[1],c2[2],c2[3]);
    }
    #pragma unroll
    for (int o = 16; o; o >>= 1){
        lmin = fminf(lmin, __shfl_xor_sync(0xffffffffu, lmin, o));
        lmax = fmaxf(lmax, __shfl_xor_sync(0xffffffffu, lmax, o));
    }
    __shared__ float smn[8], smx[8];
    int w = threadIdx.x >> 5, l = threadIdx.x & 31;
    int nw = blockDim.x >> 5;
    if (l == 0){ smn[w] = lmin; smx[w] = lmax; }
    __syncthreads();
    if (threadIdx.x == 0){
        for (int k = 1; k < nw; k++){
            lmin = fminf(lmin, smn[k]);
            lmax = fmaxf(lmax, smx[k]);
        }
        atomicMin(&g_cmm[0], fenc(lmin));
        atomicMax(&g_cmm[1], fenc(lmax));
    }
}

// ---------------- kernel 4: global min-max normalize (x4) ---------------------
__global__ void k_norm(float4* __restrict__ out4, int n4){
    float cmn = fdec(g_cmm[0]);
    float cmx = fdec(g_cmm[1]);
    float inv = __fdiv_rn(1.f, __fadd_rn(__fsub_rn(cmx, cmn), EPSF));
    int i = blockIdx.x*blockDim.x + threadIdx.x;
    if (i < n4){
        float4 v = out4[i];
        v.x = __fmul_rn(__fsub_rn(v.x, cmn), inv);
        v.y = __fmul_rn(__fsub_rn(v.y, cmn), inv);
        v.z = __fmul_rn(__fsub_rn(v.z, cmn), inv);
        v.w = __fmul_rn(__fsub_rn(v.w, cmn), inv);
        out4[i] = v;
    }
}

// ---------------- launch ------------------------------------------------------
extern "C" void kernel_launch(void* const* d_in, const int* in_sizes, int n_in,
                              void* d_out, int out_size){
    const float4* pts4  = (const float4*)d_in[0];   // [16, 200000, 3]
    const float2* pts2  = (const float2*)d_in[0];
    const float2* dens2 = (const float2*)d_in[1];   // [16, 200000, 1]
    const float2* nrm2  = (const float2*)d_in[2];   // [16, 200000, 3]
    float* out = (float*)d_out;                     // [16, 3, 224, 224]

    k_begin<<<dim3(MMB, BATCH), 256>>>(pts4);
    k_scatter<<<(BATCH*NG2 + 255)/256, 256>>>(pts2, dens2, nrm2);
    k_final<<<((BATCH*PIX)/4 + 255)/256, 256>>>(out);
    k_norm<<<((3*BATCH*PIX)/4 + 255)/256, 256>>>((float4*)out, (3*BATCH*PIX)/4);
}

// round 14
// speedup vs baseline: 1.0386x; 1.0178x over previous
#include <cuda_runtime.h>
#include <math.h>

#define BATCH 16
#define NPTS  200000
#define NG4   (NPTS/4)          // float4 groups per batch (minmax)
#define NG2   (NPTS/2)          // 2-point groups per batch (scatter)
#define SZ    224
#define PIX   (SZ*SZ)
#define EPSF  1e-8f
#define MMB   48                // minmax blocks per batch

// ---------------- scratch (static __device__, no allocations) ----------------
__device__ float4   g_acc4[BATCH*PIX];   // per pixel: (wsum, zn*w, nx*w, ny*w)
__device__ float    g_acc1[BATCH*PIX];   // per pixel: nz*w
__device__ float    g_part[BATCH*MMB*6]; // per-block partials
__device__ int      g_cnt[BATCH];        // done counters (self-resetting)
__device__ float    g_tr[BATCH*6];       // per batch: xmn,invx, ymn,invy, zmn,invz
__device__ unsigned g_cmm[2];            // global combined min,max (order-encoded)

__device__ __forceinline__ unsigned fenc(float f){
    unsigned u = __float_as_uint(f);
    return (u & 0x80000000u) ? ~u : (u | 0x80000000u);
}
__device__ __forceinline__ float fdec(unsigned u){
    return __uint_as_float((u & 0x80000000u) ? (u & 0x7fffffffu) : ~u);
}

// ---------------- kernel 1: fused zero + per-batch minmax + prep --------------
__global__ void k_begin(const float4* __restrict__ pts4){
    int b = blockIdx.y;
    int blk = blockIdx.x;
    // phase 1: zero accumulators
    {
        int nb = gridDim.x*gridDim.y;
        int gi = (b*gridDim.x + blk)*blockDim.x + threadIdx.x;
        int stride = nb*blockDim.x;
        for (int idx = gi; idx < BATCH*PIX; idx += stride){
            g_acc4[idx] = make_float4(0.f,0.f,0.f,0.f);
            g_acc1[idx] = 0.f;
        }
    }
    // phase 2: per-batch min/max over float4 groups (default policy: keep pts in L2)
    const float4* p = pts4 + (size_t)b*NG4*3;
    float mn0= INFINITY, mn1= INFINITY, mn2= INFINITY;
    float mx0=-INFINITY, mx1=-INFINITY, mx2=-INFINITY;
    for (int g = blk*blockDim.x + threadIdx.x; g < NG4; g += gridDim.x*blockDim.x){
        float4 a = p[3*g+0];           // x0 y0 z0 x1
        float4 c = p[3*g+1];           // y1 z1 x2 y2
        float4 d = p[3*g+2];           // z2 x3 y3 z3
        mn0 = fminf(mn0, fminf(fminf(a.x, a.w), fminf(c.z, d.y)));
        mx0 = fmaxf(mx0, fmaxf(fmaxf(a.x, a.w), fmaxf(c.z, d.y)));
        mn1 = fminf(mn1, fminf(fminf(a.y, c.x), fminf(c.w, d.z)));
        mx1 = fmaxf(mx1, fmaxf(fmaxf(a.y, c.x), fmaxf(c.w, d.z)));
        mn2 = fminf(mn2, fminf(fminf(a.z, c.y), fminf(d.x, d.w)));
        mx2 = fmaxf(mx2, fmaxf(fmaxf(a.z, c.y), fmaxf(d.x, d.w)));
    }
    #pragma unroll
    for (int o = 16; o; o >>= 1){
        mn0 = fminf(mn0, __shfl_xor_sync(0xffffffffu, mn0, o));
        mx0 = fmaxf(mx0, __shfl_xor_sync(0xffffffffu, mx0, o));
        mn1 = fminf(mn1, __shfl_xor_sync(0xffffffffu, mn1, o));
        mx1 = fmaxf(mx1, __shfl_xor_sync(0xffffffffu, mx1, o));
        mn2 = fminf(mn2, __shfl_xor_sync(0xffffffffu, mn2, o));
        mx2 = fmaxf(mx2, __shfl_xor_sync(0xffffffffu, mx2, o));
    }
    __shared__ float smn[8][3], smx[8][3];
    __shared__ bool s_last;
    int w = threadIdx.x >> 5, l = threadIdx.x & 31;
    int nw = blockDim.x >> 5;
    if (l == 0){
        smn[w][0]=mn0; smn[w][1]=mn1; smn[w][2]=mn2;
        smx[w][0]=mx0; smx[w][1]=mx1; smx[w][2]=mx2;
    }
    __syncthreads();
    if (threadIdx.x == 0){
        for (int k = 1; k < nw; k++){
            mn0 = fminf(mn0, smn[k][0]); mx0 = fmaxf(mx0, smx[k][0]);
            mn1 = fminf(mn1, smn[k][1]); mx1 = fmaxf(mx1, smx[k][1]);
            mn2 = fminf(mn2, smn[k][2]); mx2 = fmaxf(mx2, smx[k][2]);
        }
        float* pp = g_part + (b*MMB + blk)*6;
        pp[0]=mn0; pp[1]=mx0; pp[2]=mn1; pp[3]=mx1; pp[4]=mn2; pp[5]=mx2;
        __threadfence();
        int t = atomicAdd(&g_cnt[b], 1);
        s_last = (t == MMB-1);
    }
    __syncthreads();
    if (s_last && threadIdx.x == 0){
        float amn0= INFINITY, amn1= INFINITY, amn2= INFINITY;
        float amx0=-INFINITY, amx1=-INFINITY, amx2=-INFINITY;
        for (int k = 0; k < MMB; k++){
            const float* pp = g_part + (b*MMB + k)*6;
            amn0 = fminf(amn0, pp[0]); amx0 = fmaxf(amx0, pp[1]);
            amn1 = fminf(amn1, pp[2]); amx1 = fmaxf(amx1, pp[3]);
            amn2 = fminf(amn2, pp[4]); amx2 = fmaxf(amx2, pp[5]);
        }
        g_tr[b*6+0] = amn0;
        g_tr[b*6+1] = __fdiv_rn(1.f, __fadd_rn(__fsub_rn(amx0, amn0), EPSF));
        g_tr[b*6+2] = amn1;
        g_tr[b*6+3] = __fdiv_rn(1.f, __fadd_rn(__fsub_rn(amx1, amn1), EPSF));
        g_tr[b*6+4] = amn2;
        g_tr[b*6+5] = __fdiv_rn(1.f, __fadd_rn(__fsub_rn(amx2, amn2), EPSF));
        g_cnt[b] = 0;
        if (b == 0){ g_cmm[0] = 0xFFFFFFFFu; g_cmm[1] = 0u; }
    }
}

// ---------------- kernel 2: scatter-add, streaming loads, float atomics -------
__device__ __forceinline__ void scatter_pt(
    float x, float y, float z, float d, float nx, float ny, float nz,
    float xmn, float ivx, float ymn, float ivy, float zmn, float ivz, int base)
{
    float w = __fdiv_rn(1.f, __fadd_rn(1.f, expf(-d)));
    float fx = __fmul_rn(__fmul_rn(__fsub_rn(x, xmn), ivx), 223.0f);
    float fy = __fmul_rn(__fmul_rn(__fsub_rn(y, ymn), ivy), 223.0f);
    int xp = min(max((int)fx, 0), SZ-1);
    int yp = min(max((int)fy, 0), SZ-1);
    float zn = __fmul_rn(__fsub_rn(z, zmn), ivz);
    int pix = base + yp*SZ + xp;
    atomicAdd(&g_acc4[pix], make_float4(w, __fmul_rn(zn, w),
                                        __fmul_rn(nx, w), __fmul_rn(ny, w)));
    atomicAdd(&g_acc1[pix], __fmul_rn(nz, w));
}

__global__ void k_scatter(const float2* __restrict__ pts2,
                          const float2* __restrict__ dens2,
                          const float2* __restrict__ nrm2){
    int g = blockIdx.x*blockDim.x + threadIdx.x;   // pair of points
    if (g >= BATCH*NG2) return;
    int b = g / NG2;                                // NPTS%2==0: no straddle
    const float* tr = g_tr + b*6;
    float xmn = tr[0], ivx = tr[1];
    float ymn = tr[2], ivy = tr[3];
    float zmn = tr[4], ivz = tr[5];
    int base = b*PIX;

    // __ldcs: evict-first streaming — inputs are read exactly once here;
    // keeps the 16MB accumulator region resident in L2 for atomic service.
    float2 p0 = __ldcs(&pts2[3*g+0]);   // x0 y0
    float2 p1 = __ldcs(&pts2[3*g+1]);   // z0 x1
    float2 p2 = __ldcs(&pts2[3*g+2]);   // y1 z1
    float2 dd = __ldcs(&dens2[g]);      // d0 d1
    float2 n0 = __ldcs(&nrm2[3*g+0]);
    float2 n1 = __ldcs(&nrm2[3*g+1]);
    float2 n2 = __ldcs(&nrm2[3*g+2]);

    scatter_pt(p0.x, p0.y, p1.x, dd.x, n0.x, n0.y, n1.x, xmn,ivx,ymn,ivy,zmn,ivz, base);
    scatter_pt(p1.y, p2.x, p2.y, dd.y, n1.y, n2.x, n2.y, xmn,ivx,ymn,ivy,zmn,ivz, base);
}

// ---------------- kernel 3: per-pixel finalize (x4) + global min/max ----------
__global__ void k_final(float* __restrict__ out){
    int q = blockIdx.x*blockDim.x + threadIdx.x;   // 4 pixels
    float lmin =  INFINITY, lmax = -INFINITY;
    if (q < (BATCH*PIX)/4){
        int idx = q*4;
        int b = idx / PIX, p = idx - b*PIX;        // PIX%4==0: same b for all 4
        float4 anz = *(const float4*)&g_acc1[idx];
        float c0[4], c1[4], c2[4];
        #pragma unroll
        for (int k = 0; k < 4; k++){
            float4 a = g_acc4[idx+k];
            float az = (&anz.x)[k];
            float safe = (a.x > 0.f) ? a.x : 1.f;
            float depth = __fdiv_rn(a.y, safe);
            float nx = __fdiv_rn(a.z, safe);
            float ny = __fdiv_rn(a.w, safe);
            float nz = __fdiv_rn(az, safe);
            float ss = __fadd_rn(__fadd_rn(__fadd_rn(__fmul_rn(nx,nx), __fmul_rn(ny,ny)),
                                           __fmul_rn(nz,nz)), EPSF);
            float rn = __fsqrt_rn(ss);
            c0[k] = depth;
            c1[k] = __fmul_rn(__fadd_rn(__fdiv_rn(nx, rn), 1.f), 0.5f);
            c2[k] = __fmul_rn(__fadd_rn(__fdiv_rn(ny, rn), 1.f), 0.5f);
            lmin = fminf(lmin, fminf(c0[k], fminf(c1[k], c2[k])));
            lmax = fmaxf(lmax, fmaxf(c0[k], fmaxf(c1[k], c2[k])));
        }
        *(float4*)&out[(b*3+0)*PIX + p] = make_float4(c0[0],c0[1],c0[2],c0[3]);
        *(float4*)&out[(b*3+1)*PIX + p] = make_float4(c1[0],c1[1],c1[2],c1[3]);
        *(float4*)&out[(b*3+2)*PIX + p] = make_float4(c2[0],c2[1],c2[2],c2[3]);
    }
    #pragma unroll
    for (int o = 16; o; o >>= 1){
        lmin = fminf(lmin, __shfl_xor_sync(0xffffffffu, lmin, o));
        lmax = fmaxf(lmax, __shfl_xor_sync(0xffffffffu, lmax, o));
    }
    __shared__ float smn[8], smx[8];
    int w = threadIdx.x >> 5, l = threadIdx.x & 31;
    int nw = blockDim.x >> 5;
    if (l == 0){ smn[w] = lmin; smx[w] = lmax; }
    __syncthreads();
    if (threadIdx.x == 0){
        for (int k = 1; k < nw; k++){
            lmin = fminf(lmin, smn[k]);
            lmax = fmaxf(lmax, smx[k]);
        }
        atomicMin(&g_cmm[0], fenc(lmin));
        atomicMax(&g_cmm[1], fenc(lmax));
    }
}

// ---------------- kernel 4: global min-max normalize (4x float4/thread) -------
__global__ void k_norm(float4* __restrict__ out4, int n4){
    float cmn = fdec(g_cmm[0]);
    float cmx = fdec(g_cmm[1]);
    float inv = __fdiv_rn(1.f, __fadd_rn(__fsub_rn(cmx, cmn), EPSF));
    int i0 = (blockIdx.x*blockDim.x + threadIdx.x)*4;
    #pragma unroll
    for (int k = 0; k < 4; k++){
        int i = i0 + k;
        if (i < n4){
            float4 v = out4[i];
            v.x = __fmul_rn(__fsub_rn(v.x, cmn), inv);
            v.y = __fmul_rn(__fsub_rn(v.y, cmn), inv);
            v.z = __fmul_rn(__fsub_rn(v.z, cmn), inv);
            v.w = __fmul_rn(__fsub_rn(v.w, cmn), inv);
            out4[i] = v;
        }
    }
}

// ---------------- launch ------------------------------------------------------
extern "C" void kernel_launch(void* const* d_in, const int* in_sizes, int n_in,
                              void* d_out, int out_size){
    const float4* pts4  = (const float4*)d_in[0];   // [16, 200000, 3]
    const float2* pts2  = (const float2*)d_in[0];
    const float2* dens2 = (const float2*)d_in[1];   // [16, 200000, 1]
    const float2* nrm2  = (const float2*)d_in[2];   // [16, 200000, 3]
    float* out = (float*)d_out;                     // [16, 3, 224, 224]

    k_begin<<<dim3(MMB, BATCH), 256>>>(pts4);
    k_scatter<<<(BATCH*NG2 + 255)/256, 256>>>(pts2, dens2, nrm2);
    k_final<<<((BATCH*PIX)/4 + 255)/256, 256>>>(out);
    int n4 = (3*BATCH*PIX)/4;                        // 150528 float4s
    k_norm<<<(n4/4 + 255)/256, 256>>>((float4*)out, n4);
}

// round 15
// speedup vs baseline: 1.0595x; 1.0201x over previous
#include <cuda_runtime.h>
#include <math.h>

#define BATCH 16
#define NPTS  200000
#define NG4   (NPTS/4)          // float4 groups per batch (minmax)
#define NG2   (NPTS/2)          // 2-point groups per batch (scatter)
#define SZ    224
#define PIX   (SZ*SZ)
#define EPSF  1e-8f
#define MMB   48                // minmax blocks per batch
#define FBLK  ((BATCH*PIX)/4/256)   // 196 blocks in k_final (exact)

// ---------------- scratch (static __device__, no allocations) ----------------
__device__ float4   g_acc4[BATCH*PIX];   // per pixel: (wsum, zn*w, nx*w, ny*w)
__device__ float    g_acc1[BATCH*PIX];   // per pixel: nz*w
__device__ float    g_part[BATCH*MMB*6]; // per-block partials
__device__ int      g_cnt[BATCH];        // done counters (self-resetting)
__device__ float    g_tr[BATCH*6];       // per batch: xmn,invx, ymn,invy, zmn,invz
__device__ unsigned g_cmm[2];            // global combined min,max (order-encoded)
__device__ int      g_fcnt;              // k_final grid-barrier counter (zeroed in k_begin)

__device__ __forceinline__ unsigned fenc(float f){
    unsigned u = __float_as_uint(f);
    return (u & 0x80000000u) ? ~u : (u | 0x80000000u);
}
__device__ __forceinline__ float fdec(unsigned u){
    return __uint_as_float((u & 0x80000000u) ? (u & 0x7fffffffu) : ~u);
}

// ---------------- kernel 1: fused zero + per-batch minmax + prep --------------
__global__ void k_begin(const float4* __restrict__ pts4){
    int b = blockIdx.y;
    int blk = blockIdx.x;
    // phase 1: zero accumulators + barrier state
    {
        int nb = gridDim.x*gridDim.y;
        int gi = (b*gridDim.x + blk)*blockDim.x + threadIdx.x;
        int stride = nb*blockDim.x;
        for (int idx = gi; idx < BATCH*PIX; idx += stride){
            g_acc4[idx] = make_float4(0.f,0.f,0.f,0.f);
            g_acc1[idx] = 0.f;
        }
        if (b == 0 && blk == 0 && threadIdx.x == 0){
            g_fcnt = 0;
            g_cmm[0] = 0xFFFFFFFFu; g_cmm[1] = 0u;
        }
    }
    // phase 2: per-batch min/max over float4 groups
    const float4* p = pts4 + (size_t)b*NG4*3;
    float mn0= INFINITY, mn1= INFINITY, mn2= INFINITY;
    float mx0=-INFINITY, mx1=-INFINITY, mx2=-INFINITY;
    for (int g = blk*blockDim.x + threadIdx.x; g < NG4; g += gridDim.x*blockDim.x){
        float4 a = p[3*g+0];           // x0 y0 z0 x1
        float4 c = p[3*g+1];           // y1 z1 x2 y2
        float4 d = p[3*g+2];           // z2 x3 y3 z3
        mn0 = fminf(mn0, fminf(fminf(a.x, a.w), fminf(c.z, d.y)));
        mx0 = fmaxf(mx0, fmaxf(fmaxf(a.x, a.w), fmaxf(c.z, d.y)));
        mn1 = fminf(mn1, fminf(fminf(a.y, c.x), fminf(c.w, d.z)));
        mx1 = fmaxf(mx1, fmaxf(fmaxf(a.y, c.x), fmaxf(c.w, d.z)));
        mn2 = fminf(mn2, fminf(fminf(a.z, c.y), fminf(d.x, d.w)));
        mx2 = fmaxf(mx2, fmaxf(fmaxf(a.z, c.y), fmaxf(d.x, d.w)));
    }
    #pragma unroll
    for (int o = 16; o; o >>= 1){
        mn0 = fminf(mn0, __shfl_xor_sync(0xffffffffu, mn0, o));
        mx0 = fmaxf(mx0, __shfl_xor_sync(0xffffffffu, mx0, o));
        mn1 = fminf(mn1, __shfl_xor_sync(0xffffffffu, mn1, o));
        mx1 = fmaxf(mx1, __shfl_xor_sync(0xffffffffu, mx1, o));
        mn2 = fminf(mn2, __shfl_xor_sync(0xffffffffu, mn2, o));
        mx2 = fmaxf(mx2, __shfl_xor_sync(0xffffffffu, mx2, o));
    }
    __shared__ float smn[8][3], smx[8][3];
    __shared__ bool s_last;
    int w = threadIdx.x >> 5, l = threadIdx.x & 31;
    int nw = blockDim.x >> 5;
    if (l == 0){
        smn[w][0]=mn0; smn[w][1]=mn1; smn[w][2]=mn2;
        smx[w][0]=mx0; smx[w][1]=mx1; smx[w][2]=mx2;
    }
    __syncthreads();
    if (threadIdx.x == 0){
        for (int k = 1; k < nw; k++){
            mn0 = fminf(mn0, smn[k][0]); mx0 = fmaxf(mx0, smx[k][0]);
            mn1 = fminf(mn1, smn[k][1]); mx1 = fmaxf(mx1, smx[k][1]);
            mn2 = fminf(mn2, smn[k][2]); mx2 = fmaxf(mx2, smx[k][2]);
        }
        float* pp = g_part + (b*MMB + blk)*6;
        pp[0]=mn0; pp[1]=mx0; pp[2]=mn1; pp[3]=mx1; pp[4]=mn2; pp[5]=mx2;
        __threadfence();
        int t = atomicAdd(&g_cnt[b], 1);
        s_last = (t == MMB-1);
    }
    __syncthreads();
    if (s_last && threadIdx.x == 0){
        float amn0= INFINITY, amn1= INFINITY, amn2= INFINITY;
        float amx0=-INFINITY, amx1=-INFINITY, amx2=-INFINITY;
        for (int k = 0; k < MMB; k++){
            const float* pp = g_part + (b*MMB + k)*6;
            amn0 = fminf(amn0, pp[0]); amx0 = fmaxf(amx0, pp[1]);
            amn1 = fminf(amn1, pp[2]); amx1 = fmaxf(amx1, pp[3]);
            amn2 = fminf(amn2, pp[4]); amx2 = fmaxf(amx2, pp[5]);
        }
        g_tr[b*6+0] = amn0;
        g_tr[b*6+1] = __fdiv_rn(1.f, __fadd_rn(__fsub_rn(amx0, amn0), EPSF));
        g_tr[b*6+2] = amn1;
        g_tr[b*6+3] = __fdiv_rn(1.f, __fadd_rn(__fsub_rn(amx1, amn1), EPSF));
        g_tr[b*6+4] = amn2;
        g_tr[b*6+5] = __fdiv_rn(1.f, __fadd_rn(__fsub_rn(amx2, amn2), EPSF));
        g_cnt[b] = 0;
    }
}

// ---------------- kernel 2: scatter-add, streaming loads, float atomics -------
__device__ __forceinline__ void scatter_pt(
    float x, float y, float z, float d, float nx, float ny, float nz,
    float xmn, float ivx, float ymn, float ivy, float zmn, float ivz, int base)
{
    float w = __fdiv_rn(1.f, __fadd_rn(1.f, expf(-d)));
    float fx = __fmul_rn(__fmul_rn(__fsub_rn(x, xmn), ivx), 223.0f);
    float fy = __fmul_rn(__fmul_rn(__fsub_rn(y, ymn), ivy), 223.0f);
    int xp = min(max((int)fx, 0), SZ-1);
    int yp = min(max((int)fy, 0), SZ-1);
    float zn = __fmul_rn(__fsub_rn(z, zmn), ivz);
    int pix = base + yp*SZ + xp;
    atomicAdd(&g_acc4[pix], make_float4(w, __fmul_rn(zn, w),
                                        __fmul_rn(nx, w), __fmul_rn(ny, w)));
    atomicAdd(&g_acc1[pix], __fmul_rn(nz, w));
}

__global__ void k_scatter(const float2* __restrict__ pts2,
                          const float2* __restrict__ dens2,
                          const float2* __restrict__ nrm2){
    int g = blockIdx.x*blockDim.x + threadIdx.x;   // pair of points
    if (g >= BATCH*NG2) return;
    int b = g / NG2;                                // NPTS%2==0: no straddle
    const float* tr = g_tr + b*6;
    float xmn = tr[0], ivx = tr[1];
    float ymn = tr[2], ivy = tr[3];
    float zmn = tr[4], ivz = tr[5];
    int base = b*PIX;

    float2 p0 = __ldcs(&pts2[3*g+0]);   // x0 y0
    float2 p1 = __ldcs(&pts2[3*g+1]);   // z0 x1
    float2 p2 = __ldcs(&pts2[3*g+2]);   // y1 z1
    float2 dd = __ldcs(&dens2[g]);      // d0 d1
    float2 n0 = __ldcs(&nrm2[3*g+0]);
    float2 n1 = __ldcs(&nrm2[3*g+1]);
    float2 n2 = __ldcs(&nrm2[3*g+2]);

    scatter_pt(p0.x, p0.y, p1.x, dd.x, n0.x, n0.y, n1.x, xmn,ivx,ymn,ivy,zmn,ivz, base);
    scatter_pt(p1.y, p2.x, p2.y, dd.y, n1.y, n2.x, n2.y, xmn,ivx,ymn,ivy,zmn,ivz, base);
}

// ---------------- kernel 3: finalize + global minmax + normalize (fused) ------
// Grid is exactly FBLK=196 blocks (< single wave on 148 SMs), so a software
// grid barrier is safe: all blocks are co-resident.
__global__ void k_final(float* __restrict__ out){
    int q = blockIdx.x*blockDim.x + threadIdx.x;   // 4 pixels, no bounds needed (exact)
    int idx = q*4;
    int b = idx / PIX, p = idx - b*PIX;            // PIX%4==0: same b for all 4
    float4 anz = *(const float4*)&g_acc1[idx];
    float c0[4], c1[4], c2[4];
    float lmin =  INFINITY, lmax = -INFINITY;
    #pragma unroll
    for (int k = 0; k < 4; k++){
        float4 a = g_acc4[idx+k];
        float az = (&anz.x)[k];
        float safe = (a.x > 0.f) ? a.x : 1.f;
        float depth = __fdiv_rn(a.y, safe);
        float nx = __fdiv_rn(a.z, safe);
        float ny = __fdiv_rn(a.w, safe);
        float nz = __fdiv_rn(az, safe);
        float ss = __fadd_rn(__fadd_rn(__fadd_rn(__fmul_rn(nx,nx), __fmul_rn(ny,ny)),
                                       __fmul_rn(nz,nz)), EPSF);
        float rn = __fsqrt_rn(ss);
        c0[k] = depth;
        c1[k] = __fmul_rn(__fadd_rn(__fdiv_rn(nx, rn), 1.f), 0.5f);
        c2[k] = __fmul_rn(__fadd_rn(__fdiv_rn(ny, rn), 1.f), 0.5f);
        lmin = fminf(lmin, fminf(c0[k], fminf(c1[k], c2[k])));
        lmax = fmaxf(lmax, fmaxf(c0[k], fmaxf(c1[k], c2[k])));
    }
    // block reduce min/max
    #pragma unroll
    for (int o = 16; o; o >>= 1){
        lmin = fminf(lmin, __shfl_xor_sync(0xffffffffu, lmin, o));
        lmax = fmaxf(lmax, __shfl_xor_sync(0xffffffffu, lmax, o));
    }
    __shared__ float smn[8], smx[8];
    int w = threadIdx.x >> 5, l = threadIdx.x & 31;
    if (l == 0){ smn[w] = lmin; smx[w] = lmax; }
    __syncthreads();
    if (threadIdx.x == 0){
        for (int k = 1; k < 8; k++){
            lmin = fminf(lmin, smn[k]);
            lmax = fmaxf(lmax, smx[k]);
        }
        atomicMin(&g_cmm[0], fenc(lmin));
        atomicMax(&g_cmm[1], fenc(lmax));
        __threadfence();
        atomicAdd(&g_fcnt, 1);
        // spin until every block has contributed its min/max
        while (atomicAdd(&g_fcnt, 0) < FBLK) { }
    }
    __syncthreads();
    // all contributions visible now
    float cmn = fdec(g_cmm[0]);
    float cmx = fdec(g_cmm[1]);
    float inv = __fdiv_rn(1.f, __fadd_rn(__fsub_rn(cmx, cmn), EPSF));
    float4 v0, v1, v2;
    #pragma unroll
    for (int k = 0; k < 4; k++){
        (&v0.x)[k] = __fmul_rn(__fsub_rn(c0[k], cmn), inv);
        (&v1.x)[k] = __fmul_rn(__fsub_rn(c1[k], cmn), inv);
        (&v2.x)[k] = __fmul_rn(__fsub_rn(c2[k], cmn), inv);
    }
    *(float4*)&out[(b*3+0)*PIX + p] = v0;
    *(float4*)&out[(b*3+1)*PIX + p] = v1;
    *(float4*)&out[(b*3+2)*PIX + p] = v2;
}

// ---------------- launch ------------------------------------------------------
extern "C" void kernel_launch(void* const* d_in, const int* in_sizes, int n_in,
                              void* d_out, int out_size){
    const float4* pts4  = (const float4*)d_in[0];   // [16, 200000, 3]
    const float2* pts2  = (const float2*)d_in[0];
    const float2* dens2 = (const float2*)d_in[1];   // [16, 200000, 1]
    const float2* nrm2  = (const float2*)d_in[2];   // [16, 200000, 3]
    float* out = (float*)d_out;                     // [16, 3, 224, 224]

    k_begin<<<dim3(MMB, BATCH), 256>>>(pts4);
    k_scatter<<<(BATCH*NG2 + 255)/256, 256>>>(pts2, dens2, nrm2);
    k_final<<<FBLK, 256>>>(out);
}